// round 2
// baseline (speedup 1.0000x reference)
#include <cuda_runtime.h>
#include <cstdint>
#include <cstddef>

// ---------------------------------------------------------------------------
// Show-Attend-Tell decoder. Round 2: all GEMMs on tensor cores via
// mma.sync m16n8k8 TF32 with 3-pass hi/lo split (fp32-equivalent accuracy).
// B=128, P=196, ENC=2048, EMB=DEC=ATT=512, V=10000, T=20 (19 steps)
// ---------------------------------------------------------------------------

constexpr int B    = 128;
constexpr int P    = 196;
constexpr int ENC  = 2048;
constexpr int EMB  = 512;
constexpr int DEC  = 512;
constexpr int ATT  = 512;
constexpr int VOC  = 10000;
constexpr int T    = 20;
constexpr int NSTEP = T - 1;           // 19
constexpr int G4   = 4 * DEC;          // 2048 (i,f,g,o)
constexpr int HALLN = ATT + ENC + G4;  // 4608: [dec_att | fbeta_pre | hWhh]
constexpr int XDIM = EMB + ENC;        // 2560
constexpr int KSPLIT = 8;
constexpr int KCHUNK = XDIM / KSPLIT;  // 320

// ----------------------------- device scratch ------------------------------
__device__ float g_mean[B * ENC];
__device__ float g_hc[B * 2 * DEC];
__device__ float g_h[B * DEC];
__device__ float g_c[B * DEC];
__device__ float g_encproj[(size_t)B * P * ATT];   // 51.4 MB
__device__ float g_Wall[DEC * HALLN];              // packed [W_dec_att|W_fbeta|W_hh]
__device__ float g_ball[HALLN];
__device__ float g_Winit[ENC * 2 * DEC];           // packed [W_init_h|W_init_c]
__device__ float g_binit[2 * DEC];
__device__ float g_hall[B * HALLN];
__device__ float g_scores[B * P];
__device__ float g_alpha[B * P];
__device__ float g_x[B * XDIM];                    // [emb_t | gate*context]
__device__ float g_gpart[(size_t)KSPLIT * B * G4]; // split-K partials

// ------------------------- tf32 helpers -------------------------------------
__device__ __forceinline__ uint32_t f2tf32(float x) {
    uint32_t u;
    asm("cvt.rna.tf32.f32 %0, %1;" : "=r"(u) : "f"(x));
    return u;
}

__device__ __forceinline__ void mma_tf32(float c[4], const uint32_t a[4],
                                         const uint32_t b[2]) {
    asm volatile(
        "mma.sync.aligned.m16n8k8.row.col.f32.tf32.tf32.f32 "
        "{%0,%1,%2,%3}, {%4,%5,%6,%7}, {%8,%9}, {%0,%1,%2,%3};"
        : "+f"(c[0]), "+f"(c[1]), "+f"(c[2]), "+f"(c[3])
        : "r"(a[0]), "r"(a[1]), "r"(a[2]), "r"(a[3]), "r"(b[0]), "r"(b[1]));
}

// ------------------------------- TF32 GEMM -----------------------------------
// C[M,N] = A[M,K] @ B[K,N] (+ bias), row-major. 3-pass tf32 hi/lo split:
// C ≈ Ah*Bh + Al*Bh + Ah*Bl  (fp32-equivalent accuracy, deterministic order).
// Block tile 128x128, BK=16, 256 threads = 8 warps (4 M-slices x 2 N-slices),
// warp tile 32x64: 2 m-tiles(16) x 8 n-tiles(8).
// Split-K: blockIdx.z selects K range [z*kChunk, ...); C advances z*M*ldc.
// Requires: M % 128 == 0, kChunk % 16 == 0, N % 4 == 0 (N tail guarded).
__global__ void __launch_bounds__(256, 1)
gemm_tf32(const float* __restrict__ A, const float* __restrict__ Bm,
          float* __restrict__ C, int M, int N, int K, int ldc,
          const float* __restrict__ bias, int kChunk) {
    constexpr int BM = 128, BN = 128, BK = 16;
    __shared__ uint32_t As_h[BK][BM + 8];
    __shared__ uint32_t As_l[BK][BM + 8];
    __shared__ uint32_t Bs_h[BK][BN + 8];
    __shared__ uint32_t Bs_l[BK][BN + 8];

    const int tid  = threadIdx.x;
    const int warp = tid >> 5;
    const int lane = tid & 31;
    const int lr   = lane >> 2;   // 0..7
    const int lq   = lane & 3;    // 0..3
    const int wm   = warp & 3;    // 4 M-slices of 32
    const int wn   = warp >> 2;   // 2 N-slices of 64
    const int rowBase = blockIdx.y * BM;
    const int colBase = blockIdx.x * BN;
    const int k0 = blockIdx.z * kChunk;
    C += (size_t)blockIdx.z * M * ldc;

    float acc[2][8][4];
#pragma unroll
    for (int mt = 0; mt < 2; mt++)
#pragma unroll
        for (int nt = 0; nt < 8; nt++)
#pragma unroll
            for (int j = 0; j < 4; j++) acc[mt][nt][j] = 0.f;

    for (int kt = 0; kt < kChunk; kt += BK) {
        // ---- load A tile (128x16), split & transpose into As[k][m] ----
#pragma unroll
        for (int i = 0; i < 2; i++) {
            int idx = tid + i * 256;        // 512 float4 slots
            int r   = idx >> 2;
            int c4  = idx & 3;
            float4 v = *reinterpret_cast<const float4*>(
                &A[(size_t)(rowBase + r) * K + (k0 + kt + c4 * 4)]);
            float vv[4] = {v.x, v.y, v.z, v.w};
#pragma unroll
            for (int j = 0; j < 4; j++) {
                uint32_t hi = f2tf32(vv[j]);
                As_h[c4 * 4 + j][r] = hi;
                As_l[c4 * 4 + j][r] = f2tf32(vv[j] - __uint_as_float(hi));
            }
        }
        // ---- load B tile (16x128), split into Bs[k][n] ----
#pragma unroll
        for (int i = 0; i < 2; i++) {
            int idx = tid + i * 256;        // 512 float4 slots
            int r   = idx >> 5;
            int c4  = idx & 31;
            int gc  = colBase + c4 * 4;
            float4 v = (gc + 3 < N)
                ? *reinterpret_cast<const float4*>(
                      &Bm[(size_t)(k0 + kt + r) * N + gc])
                : make_float4(0.f, 0.f, 0.f, 0.f);
            float vv[4] = {v.x, v.y, v.z, v.w};
#pragma unroll
            for (int j = 0; j < 4; j++) {
                uint32_t hi = f2tf32(vv[j]);
                Bs_h[r][c4 * 4 + j] = hi;
                Bs_l[r][c4 * 4 + j] = f2tf32(vv[j] - __uint_as_float(hi));
            }
        }
        __syncthreads();

#pragma unroll
        for (int kk = 0; kk < BK; kk += 8) {
            uint32_t ah[2][4], al[2][4], bh[8][2], bl[8][2];
#pragma unroll
            for (int mt = 0; mt < 2; mt++) {
                int m0 = wm * 32 + mt * 16;
                ah[mt][0] = As_h[kk + lq][m0 + lr];
                ah[mt][1] = As_h[kk + lq][m0 + lr + 8];
                ah[mt][2] = As_h[kk + lq + 4][m0 + lr];
                ah[mt][3] = As_h[kk + lq + 4][m0 + lr + 8];
                al[mt][0] = As_l[kk + lq][m0 + lr];
                al[mt][1] = As_l[kk + lq][m0 + lr + 8];
                al[mt][2] = As_l[kk + lq + 4][m0 + lr];
                al[mt][3] = As_l[kk + lq + 4][m0 + lr + 8];
            }
#pragma unroll
            for (int nt = 0; nt < 8; nt++) {
                int n0 = wn * 64 + nt * 8;
                bh[nt][0] = Bs_h[kk + lq][n0 + lr];
                bh[nt][1] = Bs_h[kk + lq + 4][n0 + lr];
                bl[nt][0] = Bs_l[kk + lq][n0 + lr];
                bl[nt][1] = Bs_l[kk + lq + 4][n0 + lr];
            }
            // pass 1: Ah*Bh
#pragma unroll
            for (int mt = 0; mt < 2; mt++)
#pragma unroll
                for (int nt = 0; nt < 8; nt++)
                    mma_tf32(acc[mt][nt], ah[mt], bh[nt]);
            // pass 2: Al*Bh
#pragma unroll
            for (int mt = 0; mt < 2; mt++)
#pragma unroll
                for (int nt = 0; nt < 8; nt++)
                    mma_tf32(acc[mt][nt], al[mt], bh[nt]);
            // pass 3: Ah*Bl
#pragma unroll
            for (int mt = 0; mt < 2; mt++)
#pragma unroll
                for (int nt = 0; nt < 8; nt++)
                    mma_tf32(acc[mt][nt], ah[mt], bl[nt]);
        }
        __syncthreads();
    }

    const bool hasBias = (bias != nullptr);
#pragma unroll
    for (int mt = 0; mt < 2; mt++) {
        int r0 = rowBase + wm * 32 + mt * 16 + lr;
#pragma unroll
        for (int nt = 0; nt < 8; nt++) {
            int c0 = colBase + wn * 64 + nt * 8 + 2 * lq;
            float b0 = 0.f, b1 = 0.f;
            if (hasBias) {
                if (c0 < N)     b0 = bias[c0];
                if (c0 + 1 < N) b1 = bias[c0 + 1];
            }
            if (c0 < N) {
                C[(size_t)r0 * ldc + c0] = acc[mt][nt][0] + b0;
                C[(size_t)(r0 + 8) * ldc + c0] = acc[mt][nt][2] + b0;
            }
            if (c0 + 1 < N) {
                C[(size_t)r0 * ldc + c0 + 1] = acc[mt][nt][1] + b1;
                C[(size_t)(r0 + 8) * ldc + c0 + 1] = acc[mt][nt][3] + b1;
            }
        }
    }
}

// --------------------------- packing kernels --------------------------------
__global__ void pack_wall(const float* __restrict__ Wd,
                          const float* __restrict__ Wf,
                          const float* __restrict__ Whh) {
    int idx = blockIdx.x * 256 + threadIdx.x;
    if (idx >= DEC * HALLN) return;
    int r = idx / HALLN, c = idx % HALLN;
    float v;
    if (c < ATT)              v = Wd[r * ATT + c];
    else if (c < ATT + ENC)   v = Wf[r * ENC + (c - ATT)];
    else                      v = Whh[r * G4 + (c - ATT - ENC)];
    g_Wall[idx] = v;
}

__global__ void pack_ball(const float* __restrict__ bd,
                          const float* __restrict__ bf,
                          const float* __restrict__ bhh,
                          const float* __restrict__ bih) {
    int c = blockIdx.x * 256 + threadIdx.x;
    if (c >= HALLN) return;
    float v;
    if (c < ATT)              v = bd[c];
    else if (c < ATT + ENC)   v = bf[c - ATT];
    else                      v = bhh[c - ATT - ENC] + bih[c - ATT - ENC];
    g_ball[c] = v;
}

__global__ void pack_winit(const float* __restrict__ Wh,
                           const float* __restrict__ Wc) {
    int idx = blockIdx.x * 256 + threadIdx.x;
    if (idx >= ENC * 2 * DEC) return;
    int r = idx / (2 * DEC), c = idx % (2 * DEC);
    g_Winit[idx] = (c < DEC) ? Wh[r * DEC + c] : Wc[r * DEC + (c - DEC)];
}

__global__ void pack_binit(const float* __restrict__ bh,
                           const float* __restrict__ bc) {
    int c = blockIdx.x * 256 + threadIdx.x;
    if (c >= 2 * DEC) return;
    g_binit[c] = (c < DEC) ? bh[c] : bc[c - DEC];
}

__global__ void split_hc() {
    int idx = blockIdx.x * 256 + threadIdx.x;  // B*DEC
    int b = idx / DEC, d = idx % DEC;
    g_h[idx] = g_hc[b * 2 * DEC + d];
    g_c[idx] = g_hc[b * 2 * DEC + DEC + d];
}

// -------------------------- per-problem kernels -----------------------------
__global__ void mean_kernel(const float* __restrict__ enc_out) {
    int idx = blockIdx.x * 256 + threadIdx.x;   // B*ENC
    int b = idx / ENC, e = idx % ENC;
    const float* src = enc_out + (size_t)b * P * ENC + e;
    float s = 0.f;
#pragma unroll 4
    for (int p = 0; p < P; p++) s += src[(size_t)p * ENC];
    g_mean[idx] = s * (1.f / 196.f);
}

__global__ void embed_kernel(const float* __restrict__ emb,
                             const int* __restrict__ cap, int t) {
    int b = blockIdx.x, tid = threadIdx.x;     // 128 threads
    int cidx = cap[b * T + t];
    const float4* src = reinterpret_cast<const float4*>(emb + (size_t)cidx * EMB);
    float4* dst = reinterpret_cast<float4*>(g_x + (size_t)b * XDIM);
    dst[tid] = src[tid];
}

// scores[b,p] = sum_a relu(enc_proj[b,p,a] + dec_att[b,a]) * w_att[a] + b_att
__global__ void scores_kernel(const float* __restrict__ w_att,
                              const float* __restrict__ b_att) {
    __shared__ float s_dec[ATT];
    __shared__ float s_w[ATT];
    int b = blockIdx.x, tid = threadIdx.x;
    for (int i = tid; i < ATT; i += 256) {
        s_dec[i] = g_hall[b * HALLN + i];
        s_w[i]   = w_att[i];
    }
    __syncthreads();
    int warp = tid >> 5, lane = tid & 31;
    int p = blockIdx.y * 8 + warp;
    if (p >= P) return;
    const float* ep = &g_encproj[((size_t)(b * P + p)) * ATT];
    float s = 0.f;
#pragma unroll 4
    for (int a = lane; a < ATT; a += 32) {
        float e = ep[a] + s_dec[a];
        s += fmaxf(e, 0.f) * s_w[a];
    }
#pragma unroll
    for (int o = 16; o; o >>= 1) s += __shfl_down_sync(0xffffffffu, s, o);
    if (lane == 0) g_scores[b * P + p] = s + b_att[0];
}

__global__ void softmax_kernel() {
    __shared__ float red[256];
    int b = blockIdx.x, tid = threadIdx.x;
    float v = (tid < P) ? g_scores[b * P + tid] : -1e30f;
    red[tid] = v;
    __syncthreads();
    for (int o = 128; o; o >>= 1) {
        if (tid < o) red[tid] = fmaxf(red[tid], red[tid + o]);
        __syncthreads();
    }
    float m = red[0];
    __syncthreads();
    float e = (tid < P) ? expf(v - m) : 0.f;
    red[tid] = e;
    __syncthreads();
    for (int o = 128; o; o >>= 1) {
        if (tid < o) red[tid] += red[tid + o];
        __syncthreads();
    }
    float inv = 1.f / red[0];
    if (tid < P) g_alpha[b * P + tid] = e * inv;
}

// x[b, EMB+ch] = sigmoid(fbeta_pre[b,ch]) * sum_p alpha[b,p]*enc_out[b,p,ch]
__global__ void context_kernel(const float* __restrict__ enc_out) {
    __shared__ float s_a[P];
    int b = blockIdx.x, tid = threadIdx.x;
    int ch = blockIdx.y * 256 + tid;
    if (tid < P) s_a[tid] = g_alpha[b * P + tid];
    __syncthreads();
    const float* eb = enc_out + (size_t)b * P * ENC + ch;
    float acc = 0.f;
#pragma unroll 4
    for (int p = 0; p < P; p++) acc = fmaf(s_a[p], eb[(size_t)p * ENC], acc);
    float gpre = g_hall[b * HALLN + ATT + ch];
    float gate = 1.f / (1.f + expf(-gpre));
    g_x[(size_t)b * XDIM + EMB + ch] = gate * acc;
}

// Deterministic split-K reduce + LSTM cell, updates g_h/g_c in place.
__global__ void lstm_kernel() {
    int idx = blockIdx.x * 256 + threadIdx.x;  // B*DEC
    if (idx >= B * DEC) return;
    int b = idx / DEC, d = idx % DEC;
    const float* hallg = &g_hall[b * HALLN + ATT + ENC];  // hWhh + b_hh + b_ih
    float gi = hallg[d];
    float gf = hallg[DEC + d];
    float gg = hallg[2 * DEC + d];
    float go = hallg[3 * DEC + d];
#pragma unroll
    for (int s = 0; s < KSPLIT; s++) {
        const float* pp = &g_gpart[((size_t)s * B + b) * G4];
        gi += pp[d];
        gf += pp[DEC + d];
        gg += pp[2 * DEC + d];
        go += pp[3 * DEC + d];
    }
    float c  = g_c[idx];
    float si = 1.f / (1.f + expf(-gi));
    float sf = 1.f / (1.f + expf(-gf));
    float so = 1.f / (1.f + expf(-go));
    float cn = sf * c + si * tanhf(gg);
    float hn = so * tanhf(cn);
    g_c[idx] = cn;
    g_h[idx] = hn;
}

// ------------------------------- launcher -----------------------------------
extern "C" void kernel_launch(void* const* d_in, const int* in_sizes, int n_in,
                              void* d_out, int out_size) {
    const float* enc_out   = (const float*)d_in[0];
    const int*   captions  = (const int*)  d_in[1];
    const float* emb       = (const float*)d_in[2];
    const float* W_init_h  = (const float*)d_in[3];
    const float* b_init_h  = (const float*)d_in[4];
    const float* W_init_c  = (const float*)d_in[5];
    const float* b_init_c  = (const float*)d_in[6];
    const float* W_enc_att = (const float*)d_in[7];
    const float* b_enc_att = (const float*)d_in[8];
    const float* W_dec_att = (const float*)d_in[9];
    const float* b_dec_att = (const float*)d_in[10];
    const float* w_att     = (const float*)d_in[11];
    const float* b_att     = (const float*)d_in[12];
    const float* W_fbeta   = (const float*)d_in[13];
    const float* b_fbeta   = (const float*)d_in[14];
    const float* W_ih      = (const float*)d_in[15];
    const float* b_ih      = (const float*)d_in[16];
    const float* W_hh      = (const float*)d_in[17];
    const float* b_hh      = (const float*)d_in[18];
    const float* W_fc      = (const float*)d_in[19];
    const float* b_fc      = (const float*)d_in[20];
    float* out = (float*)d_out;

    float *p_mean, *p_hc, *p_h, *p_encproj, *p_Wall, *p_ball,
          *p_Winit, *p_binit, *p_hall, *p_x, *p_gpart;
    cudaGetSymbolAddress((void**)&p_mean,    g_mean);
    cudaGetSymbolAddress((void**)&p_hc,      g_hc);
    cudaGetSymbolAddress((void**)&p_h,       g_h);
    cudaGetSymbolAddress((void**)&p_encproj, g_encproj);
    cudaGetSymbolAddress((void**)&p_Wall,    g_Wall);
    cudaGetSymbolAddress((void**)&p_ball,    g_ball);
    cudaGetSymbolAddress((void**)&p_Winit,   g_Winit);
    cudaGetSymbolAddress((void**)&p_binit,   g_binit);
    cudaGetSymbolAddress((void**)&p_hall,    g_hall);
    cudaGetSymbolAddress((void**)&p_x,       g_x);
    cudaGetSymbolAddress((void**)&p_gpart,   g_gpart);

    // ---- one-time precompute ----
    pack_wall <<<(DEC * HALLN + 255) / 256, 256>>>(W_dec_att, W_fbeta, W_hh);
    pack_ball <<<(HALLN + 255) / 256, 256>>>(b_dec_att, b_fbeta, b_hh, b_ih);
    pack_winit<<<(ENC * 2 * DEC + 255) / 256, 256>>>(W_init_h, W_init_c);
    pack_binit<<<(2 * DEC + 255) / 256, 256>>>(b_init_h, b_init_c);
    mean_kernel<<<B * ENC / 256, 256>>>(enc_out);

    // [h0|c0] = mean @ [W_init_h|W_init_c] + [b_init_h|b_init_c]
    gemm_tf32<<<dim3(2 * DEC / 128, 1, 1), 256>>>(
        p_mean, p_Winit, p_hc, B, 2 * DEC, ENC, 2 * DEC, p_binit, ENC);
    split_hc<<<B * DEC / 256, 256>>>();

    // enc_proj = enc_out @ W_enc_att + b_enc_att   [25088, 512]
    gemm_tf32<<<dim3(ATT / 128, B * P / 128, 1), 256>>>(
        enc_out, W_enc_att, p_encproj, B * P, ATT, ENC, ATT, b_enc_att, ENC);

    // ---- decode loop ----
    for (int t = 0; t < NSTEP; t++) {
        // hall = h @ [W_dec_att|W_fbeta|W_hh] + ball    [128, 4608]
        gemm_tf32<<<dim3(HALLN / 128, 1, 1), 256>>>(
            p_h, p_Wall, p_hall, B, HALLN, DEC, HALLN, p_ball, DEC);

        embed_kernel<<<B, 128>>>(emb, captions, t);
        scores_kernel<<<dim3(B, (P + 7) / 8), 256>>>(w_att, b_att);
        softmax_kernel<<<B, 256>>>();
        context_kernel<<<dim3(B, ENC / 256), 256>>>(enc_out);

        // gates partials = x @ W_ih, split-K over XDIM=2560 into 8 chunks
        gemm_tf32<<<dim3(G4 / 128, 1, KSPLIT), 256>>>(
            p_x, W_ih, p_gpart, B, G4, XDIM, G4, nullptr, KCHUNK);

        lstm_kernel<<<B * DEC / 256, 256>>>();

        // out[:, t, :] = h_new @ W_fc + b_fc
        gemm_tf32<<<dim3((VOC + 127) / 128, 1, 1), 256>>>(
            p_h, W_fc, out + (size_t)t * VOC, B, VOC, DEC, NSTEP * VOC, b_fc,
            DEC);
    }
}

// round 4
// speedup vs baseline: 1.3170x; 1.3170x over previous
#include <cuda_runtime.h>
#include <cuda_bf16.h>
#include <cstdint>
#include <cstddef>

// ---------------------------------------------------------------------------
// Show-Attend-Tell decoder. Round 4: 3xBF16 split GEMMs (m16n8k16 mma),
// operands pre-split to bf16 hi/lo planes (weights pre-transposed to [N][K]),
// fused scores+softmax. Context reads fp32 enc_out (accuracy safety).
// All bf16 plane arrays 16B-aligned (uint4 load safety).
// ---------------------------------------------------------------------------

constexpr int B    = 128;
constexpr int P    = 196;
constexpr int ENC  = 2048;
constexpr int EMB  = 512;
constexpr int DEC  = 512;
constexpr int ATT  = 512;
constexpr int VOC  = 10000;
constexpr int T    = 20;
constexpr int NSTEP = T - 1;           // 19
constexpr int G4   = 4 * DEC;          // 2048
constexpr int HALLN = ATT + ENC + G4;  // 4608
constexpr int XDIM = EMB + ENC;        // 2560
constexpr int KSPLIT = 8;
constexpr int KCHUNK = XDIM / KSPLIT;  // 320

using bf16 = __nv_bfloat16;

// ----------------------------- device scratch ------------------------------
__device__ float g_hc[B * 2 * DEC];
__device__ float g_c[B * DEC];
__device__ __align__(16) bf16  g_h_h[B * DEC];
__device__ __align__(16) bf16  g_h_l[B * DEC];
__device__ __align__(16) bf16  g_mean_h[B * ENC];
__device__ __align__(16) bf16  g_mean_l[B * ENC];
__device__ __align__(16) bf16  g_x_h[B * XDIM];
__device__ __align__(16) bf16  g_x_l[B * XDIM];
__device__ __align__(16) bf16  g_E_h[(size_t)B * P * ENC];   // enc_out hi
__device__ __align__(16) bf16  g_E_l[(size_t)B * P * ENC];   // enc_out lo
__device__ float g_encproj[(size_t)B * P * ATT];   // fp32 (softmax path)
__device__ float g_hall[B * HALLN];
__device__ float g_alpha[B * P];
__device__ float g_gpart[(size_t)KSPLIT * B * G4];
// packed / transposed weights (bf16 hi/lo planes, [N][K] layout)
__device__ __align__(16) bf16 g_WencT_h[ATT * ENC];
__device__ __align__(16) bf16 g_WencT_l[ATT * ENC];
__device__ __align__(16) bf16 g_WinitT_h[2 * DEC * ENC];
__device__ __align__(16) bf16 g_WinitT_l[2 * DEC * ENC];
__device__ __align__(16) bf16 g_WallT_h[HALLN * DEC];
__device__ __align__(16) bf16 g_WallT_l[HALLN * DEC];
__device__ __align__(16) bf16 g_WihT_h[G4 * XDIM];
__device__ __align__(16) bf16 g_WihT_l[G4 * XDIM];
__device__ __align__(16) bf16 g_WfcT_h[VOC * DEC];
__device__ __align__(16) bf16 g_WfcT_l[VOC * DEC];
__device__ float g_ball[HALLN];
__device__ float g_binit[2 * DEC];

// ------------------------------ helpers -------------------------------------
__device__ __forceinline__ void splitbf(float x, bf16& h, bf16& l) {
    h = __float2bfloat16(x);
    l = __float2bfloat16(x - __bfloat162float(h));
}

__device__ __forceinline__ void mma_bf16(float c[4], const uint32_t a[4],
                                         const uint32_t b[2]) {
    asm volatile(
        "mma.sync.aligned.m16n8k16.row.col.f32.bf16.bf16.f32 "
        "{%0,%1,%2,%3}, {%4,%5,%6,%7}, {%8,%9}, {%0,%1,%2,%3};"
        : "+f"(c[0]), "+f"(c[1]), "+f"(c[2]), "+f"(c[3])
        : "r"(a[0]), "r"(a[1]), "r"(a[2]), "r"(a[3]), "r"(b[0]), "r"(b[1]));
}

// ------------------------------ 3xBF16 GEMM ---------------------------------
// C[M,N] = (Ah+Al)[M,K] @ (Bh+Bl)^T[N,K] (+bias). Both operands K-major bf16.
// 3 passes: Ah*Bh + Al*Bh + Ah*Bl. Block 128x128, BK=32, 256 thr, 8 warps
// (4 M-slices x 2 N-slices), warp tile 32x64.
// Split-K: z selects [z*kChunk,...), C += z*M*ldc.
// Requires M%128==0, kChunk%32==0, K%8==0. N tail guarded.
__global__ void __launch_bounds__(256, 2)
gemm_bf3(const bf16* __restrict__ Ah, const bf16* __restrict__ Al,
         const bf16* __restrict__ Bh, const bf16* __restrict__ Bl,
         float* __restrict__ C, int M, int N, int K, int ldc,
         const float* __restrict__ bias, int kChunk) {
    constexpr int PADK = 18;  // 16 u32 used per row (BK=32 bf16) + 2 pad
    __shared__ uint32_t As_h[128][PADK];
    __shared__ uint32_t As_l[128][PADK];
    __shared__ uint32_t Bs_h[128][PADK];
    __shared__ uint32_t Bs_l[128][PADK];

    const int tid  = threadIdx.x;
    const int warp = tid >> 5;
    const int lane = tid & 31;
    const int lr   = lane >> 2;    // 0..7
    const int lq   = lane & 3;     // 0..3
    const int wm   = warp & 3;     // 4 M-slices of 32
    const int wn   = warp >> 2;    // 2 N-slices of 64
    const int rowBase = blockIdx.y * 128;
    const int colBase = blockIdx.x * 128;
    const int k0 = blockIdx.z * kChunk;
    C += (size_t)blockIdx.z * M * ldc;

    float acc[2][8][4];
#pragma unroll
    for (int mt = 0; mt < 2; mt++)
#pragma unroll
        for (int nt = 0; nt < 8; nt++)
#pragma unroll
            for (int j = 0; j < 4; j++) acc[mt][nt][j] = 0.f;

    for (int kt = 0; kt < kChunk; kt += 32) {
        const int kb = k0 + kt;
        // A tile: 128 rows x 32 bf16 = 512 uint4 total
#pragma unroll
        for (int i = 0; i < 2; i++) {
            int idx = tid + i * 256;
            int r = idx >> 2, c4 = idx & 3;
            size_t off = (size_t)(rowBase + r) * K + kb + c4 * 8;
            uint4 vh = *reinterpret_cast<const uint4*>(Ah + off);
            uint4 vl = *reinterpret_cast<const uint4*>(Al + off);
            As_h[r][c4 * 4 + 0] = vh.x; As_h[r][c4 * 4 + 1] = vh.y;
            As_h[r][c4 * 4 + 2] = vh.z; As_h[r][c4 * 4 + 3] = vh.w;
            As_l[r][c4 * 4 + 0] = vl.x; As_l[r][c4 * 4 + 1] = vl.y;
            As_l[r][c4 * 4 + 2] = vl.z; As_l[r][c4 * 4 + 3] = vl.w;
        }
        // B tile: 128 n-rows x 32 bf16
#pragma unroll
        for (int i = 0; i < 2; i++) {
            int idx = tid + i * 256;
            int r = idx >> 2, c4 = idx & 3;
            int n = colBase + r;
            uint4 vh, vl;
            if (n < N) {
                size_t off = (size_t)n * K + kb + c4 * 8;
                vh = *reinterpret_cast<const uint4*>(Bh + off);
                vl = *reinterpret_cast<const uint4*>(Bl + off);
            } else {
                vh = make_uint4(0u, 0u, 0u, 0u);
                vl = make_uint4(0u, 0u, 0u, 0u);
            }
            Bs_h[r][c4 * 4 + 0] = vh.x; Bs_h[r][c4 * 4 + 1] = vh.y;
            Bs_h[r][c4 * 4 + 2] = vh.z; Bs_h[r][c4 * 4 + 3] = vh.w;
            Bs_l[r][c4 * 4 + 0] = vl.x; Bs_l[r][c4 * 4 + 1] = vl.y;
            Bs_l[r][c4 * 4 + 2] = vl.z; Bs_l[r][c4 * 4 + 3] = vl.w;
        }
        __syncthreads();

#pragma unroll
        for (int s = 0; s < 2; s++) {
            const int ps = s * 8;
            uint32_t ah[2][4], al[2][4];
#pragma unroll
            for (int mt = 0; mt < 2; mt++) {
                int m0 = wm * 32 + mt * 16;
                ah[mt][0] = As_h[m0 + lr][ps + lq];
                ah[mt][1] = As_h[m0 + lr + 8][ps + lq];
                ah[mt][2] = As_h[m0 + lr][ps + lq + 4];
                ah[mt][3] = As_h[m0 + lr + 8][ps + lq + 4];
                al[mt][0] = As_l[m0 + lr][ps + lq];
                al[mt][1] = As_l[m0 + lr + 8][ps + lq];
                al[mt][2] = As_l[m0 + lr][ps + lq + 4];
                al[mt][3] = As_l[m0 + lr + 8][ps + lq + 4];
            }
#pragma unroll
            for (int nt = 0; nt < 8; nt++) {
                int n0 = wn * 64 + nt * 8;
                uint32_t bh[2] = {Bs_h[n0 + lr][ps + lq],
                                  Bs_h[n0 + lr][ps + lq + 4]};
                uint32_t bl[2] = {Bs_l[n0 + lr][ps + lq],
                                  Bs_l[n0 + lr][ps + lq + 4]};
#pragma unroll
                for (int mt = 0; mt < 2; mt++) {
                    mma_bf16(acc[mt][nt], ah[mt], bh);
                    mma_bf16(acc[mt][nt], al[mt], bh);
                    mma_bf16(acc[mt][nt], ah[mt], bl);
                }
            }
        }
        __syncthreads();
    }

    const bool hasBias = (bias != nullptr);
#pragma unroll
    for (int mt = 0; mt < 2; mt++) {
        int r0 = rowBase + wm * 32 + mt * 16 + lr;
#pragma unroll
        for (int nt = 0; nt < 8; nt++) {
            int c0 = colBase + wn * 64 + nt * 8 + 2 * lq;
            float b0 = 0.f, b1 = 0.f;
            if (hasBias) {
                if (c0 < N)     b0 = bias[c0];
                if (c0 + 1 < N) b1 = bias[c0 + 1];
            }
            if (c0 < N) {
                C[(size_t)r0 * ldc + c0] = acc[mt][nt][0] + b0;
                C[(size_t)(r0 + 8) * ldc + c0] = acc[mt][nt][2] + b0;
            }
            if (c0 + 1 < N) {
                C[(size_t)r0 * ldc + c0 + 1] = acc[mt][nt][1] + b1;
                C[(size_t)(r0 + 8) * ldc + c0 + 1] = acc[mt][nt][3] + b1;
            }
        }
    }
}

// ---------------------------- pack kernels ----------------------------------
constexpr int S0 = ATT * ENC;            // WencT
constexpr int S1 = 2 * DEC * ENC;        // WinitT
constexpr int S2 = HALLN * DEC;          // WallT
constexpr int S3 = G4 * XDIM;            // WihT
constexpr int S4 = VOC * DEC;            // WfcT
constexpr int STOT = S0 + S1 + S2 + S3 + S4;

__global__ void pack_weights(const float* __restrict__ Wenc,
                             const float* __restrict__ Wih_init,
                             const float* __restrict__ Wic_init,
                             const float* __restrict__ Wd,
                             const float* __restrict__ Wf,
                             const float* __restrict__ Whh,
                             const float* __restrict__ Wih,
                             const float* __restrict__ Wfc) {
    int idx = blockIdx.x * 256 + threadIdx.x;
    if (idx >= STOT) return;
    float v; bf16 *dh, *dl; int j = idx;
    if (j < S0) {                         // [ATT][ENC] <- W_enc_att[ENC][ATT]
        int n = j / ENC, k = j % ENC;
        v = Wenc[(size_t)k * ATT + n];
        dh = &g_WencT_h[j]; dl = &g_WencT_l[j];
    } else if ((j -= S0) < S1) {          // [1024][ENC] <- W_init_{h,c}
        int n = j / ENC, k = j % ENC;
        v = (n < DEC) ? Wih_init[(size_t)k * DEC + n]
                      : Wic_init[(size_t)k * DEC + (n - DEC)];
        dh = &g_WinitT_h[j]; dl = &g_WinitT_l[j];
    } else if ((j -= S1) < S2) {          // [HALLN][DEC]
        int n = j / DEC, k = j % DEC;
        if (n < ATT)            v = Wd[(size_t)k * ATT + n];
        else if (n < ATT + ENC) v = Wf[(size_t)k * ENC + (n - ATT)];
        else                    v = Whh[(size_t)k * G4 + (n - ATT - ENC)];
        dh = &g_WallT_h[j]; dl = &g_WallT_l[j];
    } else if ((j -= S2) < S3) {          // [G4][XDIM]
        int n = j / XDIM, k = j % XDIM;
        v = Wih[(size_t)k * G4 + n];
        dh = &g_WihT_h[j]; dl = &g_WihT_l[j];
    } else {                              // [VOC][DEC]
        j -= S3;
        int n = j / DEC, k = j % DEC;
        v = Wfc[(size_t)k * VOC + n];
        dh = &g_WfcT_h[j]; dl = &g_WfcT_l[j];
    }
    splitbf(v, *dh, *dl);
}

__global__ void pack_bias(const float* __restrict__ bd,
                          const float* __restrict__ bf,
                          const float* __restrict__ bhh,
                          const float* __restrict__ bih,
                          const float* __restrict__ bh0,
                          const float* __restrict__ bc0) {
    int c = blockIdx.x * 256 + threadIdx.x;
    if (c < HALLN) {
        float v;
        if (c < ATT)            v = bd[c];
        else if (c < ATT + ENC) v = bf[c - ATT];
        else                    v = bhh[c - ATT - ENC] + bih[c - ATT - ENC];
        g_ball[c] = v;
    } else if (c < HALLN + 2 * DEC) {
        int q = c - HALLN;
        g_binit[q] = (q < DEC) ? bh0[q] : bc0[q - DEC];
    }
}

__global__ void split_encout(const float* __restrict__ enc_out) {
    size_t i = (size_t)blockIdx.x * 256 + threadIdx.x;   // float4 index
    float4 v = reinterpret_cast<const float4*>(enc_out)[i];
    bf16 h0, l0, h1, l1, h2, l2, h3, l3;
    splitbf(v.x, h0, l0); splitbf(v.y, h1, l1);
    splitbf(v.z, h2, l2); splitbf(v.w, h3, l3);
    __nv_bfloat162* Eh2 = reinterpret_cast<__nv_bfloat162*>(g_E_h);
    __nv_bfloat162* El2 = reinterpret_cast<__nv_bfloat162*>(g_E_l);
    Eh2[i * 2 + 0] = __nv_bfloat162(h0, h1);
    Eh2[i * 2 + 1] = __nv_bfloat162(h2, h3);
    El2[i * 2 + 0] = __nv_bfloat162(l0, l1);
    El2[i * 2 + 1] = __nv_bfloat162(l2, l3);
}

__global__ void mean_kernel(const float* __restrict__ enc_out) {
    int idx = blockIdx.x * 256 + threadIdx.x;   // B*ENC
    int b = idx / ENC, e = idx % ENC;
    const float* src = enc_out + (size_t)b * P * ENC + e;
    float s = 0.f;
#pragma unroll 4
    for (int p = 0; p < P; p++) s += src[(size_t)p * ENC];
    splitbf(s * (1.f / 196.f), g_mean_h[idx], g_mean_l[idx]);
}

__global__ void split_hc() {
    int idx = blockIdx.x * 256 + threadIdx.x;  // B*DEC
    int b = idx / DEC, d = idx % DEC;
    splitbf(g_hc[b * 2 * DEC + d], g_h_h[idx], g_h_l[idx]);
    g_c[idx] = g_hc[b * 2 * DEC + DEC + d];
}

// -------------------------- per-step kernels --------------------------------
__global__ void embed_kernel(const float* __restrict__ emb,
                             const int* __restrict__ cap, int t) {
    int b = blockIdx.x, tid = threadIdx.x;     // 128 threads
    int cidx = cap[b * T + t];
    const float4* src = reinterpret_cast<const float4*>(emb + (size_t)cidx * EMB);
    float4 v = src[tid];
    int o = b * XDIM + tid * 4;
    splitbf(v.x, g_x_h[o + 0], g_x_l[o + 0]);
    splitbf(v.y, g_x_h[o + 1], g_x_l[o + 1]);
    splitbf(v.z, g_x_h[o + 2], g_x_l[o + 2]);
    splitbf(v.w, g_x_h[o + 3], g_x_l[o + 3]);
}

// Fused scores + softmax: one block per batch row.
__global__ void scores_softmax_kernel(const float* __restrict__ w_att,
                                      const float* __restrict__ b_att) {
    __shared__ float s_dec[ATT];
    __shared__ float s_w[ATT];
    __shared__ float s_sc[P];
    __shared__ float red[256];
    int b = blockIdx.x, tid = threadIdx.x;
    int warp = tid >> 5, lane = tid & 31;
    for (int i = tid; i < ATT; i += 256) {
        s_dec[i] = g_hall[b * HALLN + i];
        s_w[i]   = w_att[i];
    }
    __syncthreads();
    float batt = b_att[0];
    for (int p = warp; p < P; p += 8) {
        const float* ep = &g_encproj[((size_t)(b * P + p)) * ATT];
        float s = 0.f;
#pragma unroll 4
        for (int a = lane; a < ATT; a += 32) {
            float e = ep[a] + s_dec[a];
            s += fmaxf(e, 0.f) * s_w[a];
        }
#pragma unroll
        for (int o = 16; o; o >>= 1) s += __shfl_down_sync(0xffffffffu, s, o);
        if (lane == 0) s_sc[p] = s + batt;
    }
    __syncthreads();
    float v = (tid < P) ? s_sc[tid] : -1e30f;
    red[tid] = v;
    __syncthreads();
    for (int o = 128; o; o >>= 1) {
        if (tid < o) red[tid] = fmaxf(red[tid], red[tid + o]);
        __syncthreads();
    }
    float m = red[0];
    __syncthreads();
    float e = (tid < P) ? expf(v - m) : 0.f;
    red[tid] = e;
    __syncthreads();
    for (int o = 128; o; o >>= 1) {
        if (tid < o) red[tid] += red[tid + o];
        __syncthreads();
    }
    if (tid < P) g_alpha[b * P + tid] = e / red[0];
}

// x[b, EMB+ch] = sigmoid(fbeta) * sum_p alpha[b,p]*enc_out[b,p,ch]  (fp32)
__global__ void context_kernel(const float* __restrict__ enc_out) {
    __shared__ float s_a[P];
    int b = blockIdx.x, tid = threadIdx.x;
    int ch = blockIdx.y * 256 + tid;
    if (tid < P) s_a[tid] = g_alpha[b * P + tid];
    __syncthreads();
    const float* eb = enc_out + (size_t)b * P * ENC + ch;
    float acc = 0.f;
#pragma unroll 4
    for (int p = 0; p < P; p++) acc = fmaf(s_a[p], eb[(size_t)p * ENC], acc);
    float gate = 1.f / (1.f + expf(-g_hall[b * HALLN + ATT + ch]));
    int o = b * XDIM + EMB + ch;
    splitbf(gate * acc, g_x_h[o], g_x_l[o]);
}

// Deterministic split-K reduce + LSTM cell; writes h planes + c.
__global__ void lstm_kernel() {
    int idx = blockIdx.x * 256 + threadIdx.x;  // B*DEC
    int b = idx / DEC, d = idx % DEC;
    const float* hallg = &g_hall[b * HALLN + ATT + ENC];
    float gi = hallg[d];
    float gf = hallg[DEC + d];
    float gg = hallg[2 * DEC + d];
    float go = hallg[3 * DEC + d];
#pragma unroll
    for (int s = 0; s < KSPLIT; s++) {
        const float* pp = &g_gpart[((size_t)s * B + b) * G4];
        gi += pp[d];
        gf += pp[DEC + d];
        gg += pp[2 * DEC + d];
        go += pp[3 * DEC + d];
    }
    float c  = g_c[idx];
    float si = 1.f / (1.f + expf(-gi));
    float sf = 1.f / (1.f + expf(-gf));
    float so = 1.f / (1.f + expf(-go));
    float cn = sf * c + si * tanhf(gg);
    float hn = so * tanhf(cn);
    g_c[idx] = cn;
    splitbf(hn, g_h_h[idx], g_h_l[idx]);
}

// ------------------------------- launcher -----------------------------------
extern "C" void kernel_launch(void* const* d_in, const int* in_sizes, int n_in,
                              void* d_out, int out_size) {
    const float* enc_out   = (const float*)d_in[0];
    const int*   captions  = (const int*)  d_in[1];
    const float* emb       = (const float*)d_in[2];
    const float* W_init_h  = (const float*)d_in[3];
    const float* b_init_h  = (const float*)d_in[4];
    const float* W_init_c  = (const float*)d_in[5];
    const float* b_init_c  = (const float*)d_in[6];
    const float* W_enc_att = (const float*)d_in[7];
    const float* b_enc_att = (const float*)d_in[8];
    const float* W_dec_att = (const float*)d_in[9];
    const float* b_dec_att = (const float*)d_in[10];
    const float* w_att     = (const float*)d_in[11];
    const float* b_att     = (const float*)d_in[12];
    const float* W_fbeta   = (const float*)d_in[13];
    const float* b_fbeta   = (const float*)d_in[14];
    const float* W_ih      = (const float*)d_in[15];
    const float* b_ih      = (const float*)d_in[16];
    const float* W_hh      = (const float*)d_in[17];
    const float* b_hh      = (const float*)d_in[18];
    const float* W_fc      = (const float*)d_in[19];
    const float* b_fc      = (const float*)d_in[20];
    float* out = (float*)d_out;

    bf16 *pMh, *pMl, *pHh, *pHl, *pXh, *pXl, *pEh, *pEl;
    bf16 *pWencH, *pWencL, *pWinH, *pWinL, *pWallH, *pWallL,
         *pWihH, *pWihL, *pWfcH, *pWfcL;
    float *p_hc, *p_encproj, *p_hall, *p_gpart, *p_ball, *p_binit;
    cudaGetSymbolAddress((void**)&pEh, g_E_h);
    cudaGetSymbolAddress((void**)&pEl, g_E_l);
    cudaGetSymbolAddress((void**)&pMh, g_mean_h);
    cudaGetSymbolAddress((void**)&pMl, g_mean_l);
    cudaGetSymbolAddress((void**)&pHh, g_h_h);
    cudaGetSymbolAddress((void**)&pHl, g_h_l);
    cudaGetSymbolAddress((void**)&pXh, g_x_h);
    cudaGetSymbolAddress((void**)&pXl, g_x_l);
    cudaGetSymbolAddress((void**)&pWencH, g_WencT_h);
    cudaGetSymbolAddress((void**)&pWencL, g_WencT_l);
    cudaGetSymbolAddress((void**)&pWinH, g_WinitT_h);
    cudaGetSymbolAddress((void**)&pWinL, g_WinitT_l);
    cudaGetSymbolAddress((void**)&pWallH, g_WallT_h);
    cudaGetSymbolAddress((void**)&pWallL, g_WallT_l);
    cudaGetSymbolAddress((void**)&pWihH, g_WihT_h);
    cudaGetSymbolAddress((void**)&pWihL, g_WihT_l);
    cudaGetSymbolAddress((void**)&pWfcH, g_WfcT_h);
    cudaGetSymbolAddress((void**)&pWfcL, g_WfcT_l);
    cudaGetSymbolAddress((void**)&p_hc, g_hc);
    cudaGetSymbolAddress((void**)&p_encproj, g_encproj);
    cudaGetSymbolAddress((void**)&p_hall, g_hall);
    cudaGetSymbolAddress((void**)&p_gpart, g_gpart);
    cudaGetSymbolAddress((void**)&p_ball, g_ball);
    cudaGetSymbolAddress((void**)&p_binit, g_binit);

    // ---- one-time precompute (launch #4 = enc_proj GEMM for ncu) ----
    pack_weights<<<(STOT + 255) / 256, 256>>>(W_enc_att, W_init_h, W_init_c,
                                              W_dec_att, W_fbeta, W_hh, W_ih,
                                              W_fc);
    pack_bias<<<(HALLN + 2 * DEC + 255) / 256, 256>>>(b_dec_att, b_fbeta, b_hh,
                                                      b_ih, b_init_h, b_init_c);
    split_encout<<<(int)(((size_t)B * P * ENC / 4 + 255) / 256), 256>>>(enc_out);

    // enc_proj = enc_out @ W_enc_att + b  -> fp32 [25088, 512]
    gemm_bf3<<<dim3(ATT / 128, B * P / 128, 1), 256>>>(
        pEh, pEl, pWencH, pWencL, p_encproj, B * P, ATT, ENC, ATT, b_enc_att,
        ENC);

    mean_kernel<<<B * ENC / 256, 256>>>(enc_out);

    // [h0|c0] = mean @ [W_init_h|W_init_c] + b
    gemm_bf3<<<dim3(2 * DEC / 128, 1, 1), 256>>>(
        pMh, pMl, pWinH, pWinL, p_hc, B, 2 * DEC, ENC, 2 * DEC, p_binit, ENC);
    split_hc<<<B * DEC / 256, 256>>>();

    // ---- decode loop ----
    for (int t = 0; t < NSTEP; t++) {
        // hall = h @ [W_dec_att|W_fbeta|W_hh] + ball    [128, 4608]
        gemm_bf3<<<dim3(HALLN / 128, 1, 1), 256>>>(
            pHh, pHl, pWallH, pWallL, p_hall, B, HALLN, DEC, HALLN, p_ball,
            DEC);

        embed_kernel<<<B, 128>>>(emb, captions, t);
        scores_softmax_kernel<<<B, 256>>>(w_att, b_att);
        context_kernel<<<dim3(B, ENC / 256), 256>>>(enc_out);

        // gates partials = x @ W_ih, split-K over XDIM
        gemm_bf3<<<dim3(G4 / 128, 1, KSPLIT), 256>>>(
            pXh, pXl, pWihH, pWihL, p_gpart, B, G4, XDIM, G4, nullptr, KCHUNK);

        lstm_kernel<<<B * DEC / 256, 256>>>();

        // out[:, t, :] = h_new @ W_fc + b_fc
        gemm_bf3<<<dim3((VOC + 127) / 128, 1, 1), 256>>>(
            pHh, pHl, pWfcH, pWfcL, out + (size_t)t * VOC, B, VOC, DEC,
            NSTEP * VOC, b_fc, DEC);
    }
}

// round 5
// speedup vs baseline: 1.5128x; 1.1487x over previous
#include <cuda_runtime.h>
#include <cuda_bf16.h>
#include <cstdint>
#include <cstddef>

// ---------------------------------------------------------------------------
// Show-Attend-Tell decoder. Round 5: 3xBF16 split GEMM upgraded with
// ldmatrix.x4 fragment loads (4x fewer LDS wavefronts; R4 was L1-bound at 70%)
// and cp.async 2-stage double buffering (hides GMEM latency in the small
// per-step GEMMs). Everything else as R4.
// ---------------------------------------------------------------------------

constexpr int B    = 128;
constexpr int P    = 196;
constexpr int ENC  = 2048;
constexpr int EMB  = 512;
constexpr int DEC  = 512;
constexpr int ATT  = 512;
constexpr int VOC  = 10000;
constexpr int T    = 20;
constexpr int NSTEP = T - 1;           // 19
constexpr int G4   = 4 * DEC;          // 2048
constexpr int HALLN = ATT + ENC + G4;  // 4608
constexpr int XDIM = EMB + ENC;        // 2560
constexpr int KSPLIT = 8;
constexpr int KCHUNK = XDIM / KSPLIT;  // 320

using bf16 = __nv_bfloat16;

// ----------------------------- device scratch ------------------------------
__device__ float g_hc[B * 2 * DEC];
__device__ float g_c[B * DEC];
__device__ __align__(16) bf16  g_h_h[B * DEC];
__device__ __align__(16) bf16  g_h_l[B * DEC];
__device__ __align__(16) bf16  g_mean_h[B * ENC];
__device__ __align__(16) bf16  g_mean_l[B * ENC];
__device__ __align__(16) bf16  g_x_h[B * XDIM];
__device__ __align__(16) bf16  g_x_l[B * XDIM];
__device__ __align__(16) bf16  g_E_h[(size_t)B * P * ENC];   // enc_out hi
__device__ __align__(16) bf16  g_E_l[(size_t)B * P * ENC];   // enc_out lo
__device__ float g_encproj[(size_t)B * P * ATT];   // fp32 (softmax path)
__device__ float g_hall[B * HALLN];
__device__ float g_alpha[B * P];
__device__ float g_gpart[(size_t)KSPLIT * B * G4];
// packed / transposed weights (bf16 hi/lo planes, [N][K] layout)
__device__ __align__(16) bf16 g_WencT_h[ATT * ENC];
__device__ __align__(16) bf16 g_WencT_l[ATT * ENC];
__device__ __align__(16) bf16 g_WinitT_h[2 * DEC * ENC];
__device__ __align__(16) bf16 g_WinitT_l[2 * DEC * ENC];
__device__ __align__(16) bf16 g_WallT_h[HALLN * DEC];
__device__ __align__(16) bf16 g_WallT_l[HALLN * DEC];
__device__ __align__(16) bf16 g_WihT_h[G4 * XDIM];
__device__ __align__(16) bf16 g_WihT_l[G4 * XDIM];
__device__ __align__(16) bf16 g_WfcT_h[VOC * DEC];
__device__ __align__(16) bf16 g_WfcT_l[VOC * DEC];
__device__ float g_ball[HALLN];
__device__ float g_binit[2 * DEC];

// ------------------------------ helpers -------------------------------------
__device__ __forceinline__ void splitbf(float x, bf16& h, bf16& l) {
    h = __float2bfloat16(x);
    l = __float2bfloat16(x - __bfloat162float(h));
}

__device__ __forceinline__ void mma_bf16(float c[4], const uint32_t a[4],
                                         const uint32_t b[2]) {
    asm volatile(
        "mma.sync.aligned.m16n8k16.row.col.f32.bf16.bf16.f32 "
        "{%0,%1,%2,%3}, {%4,%5,%6,%7}, {%8,%9}, {%0,%1,%2,%3};"
        : "+f"(c[0]), "+f"(c[1]), "+f"(c[2]), "+f"(c[3])
        : "r"(a[0]), "r"(a[1]), "r"(a[2]), "r"(a[3]), "r"(b[0]), "r"(b[1]));
}

__device__ __forceinline__ void ldsm4(uint32_t& r0, uint32_t& r1, uint32_t& r2,
                                      uint32_t& r3, uint32_t addr) {
    asm volatile(
        "ldmatrix.sync.aligned.m8n8.x4.shared.b16 {%0,%1,%2,%3}, [%4];"
        : "=r"(r0), "=r"(r1), "=r"(r2), "=r"(r3) : "r"(addr));
}

__device__ __forceinline__ void cpasync16(uint32_t dst, const void* src) {
    asm volatile("cp.async.cg.shared.global [%0], [%1], 16;"
                 :: "r"(dst), "l"(src));
}

// ------------------------------ 3xBF16 GEMM ---------------------------------
// C[M,N] = (Ah+Al)[M,K] @ (Bh+Bl)^T[N,K] (+bias). Both operands K-major bf16.
// 3 passes: Ah*Bh + Al*Bh + Ah*Bl. Block 128x128, BK=32, 256 thr, 8 warps
// (4 M-slices x 2 N-slices), warp tile 32x64. cp.async double buffer +
// ldmatrix.x4 fragment loads, PADK=20 u32 row stride (bank-conflict-free).
// Split-K: z selects [z*kChunk,...), C += z*M*ldc.
// Requires M%128==0, kChunk%32==0, K%8==0. N tail: rows clamped (cols unused).
constexpr int PADK  = 20;               // u32 per smem row (16 data + 4 pad)
constexpr int PLANE = 128 * PADK;       // u32 per plane
constexpr int STAGE = 4 * PLANE;        // u32 per stage (Ah|Al|Bh|Bl)
constexpr int GEMM_SMEM = 2 * STAGE * 4;  // bytes (81920)

extern __shared__ uint32_t dynsm[];

__global__ void __launch_bounds__(256, 2)
gemm_bf3(const bf16* __restrict__ Ah, const bf16* __restrict__ Al,
         const bf16* __restrict__ Bh, const bf16* __restrict__ Bl,
         float* __restrict__ C, int M, int N, int K, int ldc,
         const float* __restrict__ bias, int kChunk) {
    const int tid  = threadIdx.x;
    const int warp = tid >> 5;
    const int lane = tid & 31;
    const int lr   = lane >> 2;    // 0..7
    const int lq   = lane & 3;     // 0..3
    const int wm   = warp & 3;     // 4 M-slices of 32
    const int wn   = warp >> 2;    // 2 N-slices of 64
    const int rowBase = blockIdx.y * 128;
    const int colBase = blockIdx.x * 128;
    const int k0 = blockIdx.z * kChunk;
    const int nIter = kChunk / 32;
    C += (size_t)blockIdx.z * M * ldc;

    const uint32_t smemBase = (uint32_t)__cvta_generic_to_shared(dynsm);

    // cp.async task split: 512 tasks of 16B per plane; tid handles 2.
    const int tr = tid >> 1;               // row 0..127
    const int tc = tid & 1;                // chunk pair base
    // per-thread: rows tr, chunks {tc*2, tc*2+1}  (2 chunks x 16B = 32B)
    auto load_stage = [&](int it, int stg) {
        const int kb = k0 + it * 32;
        const uint32_t sb = smemBase + (uint32_t)(stg * STAGE) * 4;
        const int nclamp = min(colBase + tr, N - 1);
        const size_t offA = (size_t)(rowBase + tr) * K + kb;
        const size_t offB = (size_t)nclamp * K + kb;
#pragma unroll
        for (int c = 0; c < 2; c++) {
            const int ch = tc * 2 + c;                       // 0..3
            const uint32_t d = (uint32_t)(tr * PADK + ch * 4) * 4;
            cpasync16(sb + d,                       Ah + offA + ch * 8);
            cpasync16(sb + PLANE * 4 + d,           Al + offA + ch * 8);
            cpasync16(sb + 2u * PLANE * 4 + d,      Bh + offB + ch * 8);
            cpasync16(sb + 3u * PLANE * 4 + d,      Bl + offB + ch * 8);
        }
    };

    // ldmatrix per-lane address components (u32 units)
    const int aRow = (lane & 7) + ((lane >> 3) & 1) * 8;
    const int aK   = ((lane >> 4) & 1) * 4;
    const int bRow = (lane & 7) + ((lane >> 4) & 1) * 8;
    const int bK   = ((lane >> 3) & 1) * 4;

    float acc[2][8][4];
#pragma unroll
    for (int mt = 0; mt < 2; mt++)
#pragma unroll
        for (int nt = 0; nt < 8; nt++)
#pragma unroll
            for (int j = 0; j < 4; j++) acc[mt][nt][j] = 0.f;

    load_stage(0, 0);
    asm volatile("cp.async.commit_group;");

    for (int it = 0; it < nIter; it++) {
        if (it + 1 < nIter) {
            load_stage(it + 1, (it + 1) & 1);
            asm volatile("cp.async.commit_group;");
            asm volatile("cp.async.wait_group 1;");
        } else {
            asm volatile("cp.async.wait_group 0;");
        }
        __syncthreads();

        const uint32_t sb = smemBase + (uint32_t)((it & 1) * STAGE) * 4;
#pragma unroll
        for (int s = 0; s < 2; s++) {
            const uint32_t ks = (uint32_t)(s * 8) * 4;
            uint32_t ah[2][4], al[2][4], bh[8][2], bl[8][2];
#pragma unroll
            for (int mt = 0; mt < 2; mt++) {
                uint32_t ra = (uint32_t)((wm * 32 + mt * 16 + aRow) * PADK +
                                         aK) * 4 + ks;
                ldsm4(ah[mt][0], ah[mt][1], ah[mt][2], ah[mt][3], sb + ra);
                ldsm4(al[mt][0], al[mt][1], al[mt][2], al[mt][3],
                      sb + PLANE * 4 + ra);
            }
#pragma unroll
            for (int np = 0; np < 4; np++) {
                uint32_t rb = (uint32_t)((wn * 64 + np * 16 + bRow) * PADK +
                                         bK) * 4 + ks;
                ldsm4(bh[2 * np][0], bh[2 * np][1], bh[2 * np + 1][0],
                      bh[2 * np + 1][1], sb + 2u * PLANE * 4 + rb);
                ldsm4(bl[2 * np][0], bl[2 * np][1], bl[2 * np + 1][0],
                      bl[2 * np + 1][1], sb + 3u * PLANE * 4 + rb);
            }
#pragma unroll
            for (int nt = 0; nt < 8; nt++)
#pragma unroll
                for (int mt = 0; mt < 2; mt++) {
                    mma_bf16(acc[mt][nt], ah[mt], bh[nt]);
                    mma_bf16(acc[mt][nt], al[mt], bh[nt]);
                    mma_bf16(acc[mt][nt], ah[mt], bl[nt]);
                }
        }
        __syncthreads();
    }

    const bool hasBias = (bias != nullptr);
#pragma unroll
    for (int mt = 0; mt < 2; mt++) {
        int r0 = rowBase + wm * 32 + mt * 16 + lr;
#pragma unroll
        for (int nt = 0; nt < 8; nt++) {
            int c0 = colBase + wn * 64 + nt * 8 + 2 * lq;
            float b0 = 0.f, b1 = 0.f;
            if (hasBias) {
                if (c0 < N)     b0 = bias[c0];
                if (c0 + 1 < N) b1 = bias[c0 + 1];
            }
            if (c0 < N) {
                C[(size_t)r0 * ldc + c0] = acc[mt][nt][0] + b0;
                C[(size_t)(r0 + 8) * ldc + c0] = acc[mt][nt][2] + b0;
            }
            if (c0 + 1 < N) {
                C[(size_t)r0 * ldc + c0 + 1] = acc[mt][nt][1] + b1;
                C[(size_t)(r0 + 8) * ldc + c0 + 1] = acc[mt][nt][3] + b1;
            }
        }
    }
}

// ---------------------------- pack kernels ----------------------------------
constexpr int S0 = ATT * ENC;            // WencT
constexpr int S1 = 2 * DEC * ENC;        // WinitT
constexpr int S2 = HALLN * DEC;          // WallT
constexpr int S3 = G4 * XDIM;            // WihT
constexpr int S4 = VOC * DEC;            // WfcT
constexpr int STOT = S0 + S1 + S2 + S3 + S4;

__global__ void pack_weights(const float* __restrict__ Wenc,
                             const float* __restrict__ Wih_init,
                             const float* __restrict__ Wic_init,
                             const float* __restrict__ Wd,
                             const float* __restrict__ Wf,
                             const float* __restrict__ Whh,
                             const float* __restrict__ Wih,
                             const float* __restrict__ Wfc) {
    int idx = blockIdx.x * 256 + threadIdx.x;
    if (idx >= STOT) return;
    float v; bf16 *dh, *dl; int j = idx;
    if (j < S0) {                         // [ATT][ENC] <- W_enc_att[ENC][ATT]
        int n = j / ENC, k = j % ENC;
        v = Wenc[(size_t)k * ATT + n];
        dh = &g_WencT_h[j]; dl = &g_WencT_l[j];
    } else if ((j -= S0) < S1) {          // [1024][ENC] <- W_init_{h,c}
        int n = j / ENC, k = j % ENC;
        v = (n < DEC) ? Wih_init[(size_t)k * DEC + n]
                      : Wic_init[(size_t)k * DEC + (n - DEC)];
        dh = &g_WinitT_h[j]; dl = &g_WinitT_l[j];
    } else if ((j -= S1) < S2) {          // [HALLN][DEC]
        int n = j / DEC, k = j % DEC;
        if (n < ATT)            v = Wd[(size_t)k * ATT + n];
        else if (n < ATT + ENC) v = Wf[(size_t)k * ENC + (n - ATT)];
        else                    v = Whh[(size_t)k * G4 + (n - ATT - ENC)];
        dh = &g_WallT_h[j]; dl = &g_WallT_l[j];
    } else if ((j -= S2) < S3) {          // [G4][XDIM]
        int n = j / XDIM, k = j % XDIM;
        v = Wih[(size_t)k * G4 + n];
        dh = &g_WihT_h[j]; dl = &g_WihT_l[j];
    } else {                              // [VOC][DEC]
        j -= S3;
        int n = j / DEC, k = j % DEC;
        v = Wfc[(size_t)k * VOC + n];
        dh = &g_WfcT_h[j]; dl = &g_WfcT_l[j];
    }
    splitbf(v, *dh, *dl);
}

__global__ void pack_bias(const float* __restrict__ bd,
                          const float* __restrict__ bf,
                          const float* __restrict__ bhh,
                          const float* __restrict__ bih,
                          const float* __restrict__ bh0,
                          const float* __restrict__ bc0) {
    int c = blockIdx.x * 256 + threadIdx.x;
    if (c < HALLN) {
        float v;
        if (c < ATT)            v = bd[c];
        else if (c < ATT + ENC) v = bf[c - ATT];
        else                    v = bhh[c - ATT - ENC] + bih[c - ATT - ENC];
        g_ball[c] = v;
    } else if (c < HALLN + 2 * DEC) {
        int q = c - HALLN;
        g_binit[q] = (q < DEC) ? bh0[q] : bc0[q - DEC];
    }
}

__global__ void split_encout(const float* __restrict__ enc_out) {
    size_t i = (size_t)blockIdx.x * 256 + threadIdx.x;   // float4 index
    float4 v = reinterpret_cast<const float4*>(enc_out)[i];
    bf16 h0, l0, h1, l1, h2, l2, h3, l3;
    splitbf(v.x, h0, l0); splitbf(v.y, h1, l1);
    splitbf(v.z, h2, l2); splitbf(v.w, h3, l3);
    __nv_bfloat162* Eh2 = reinterpret_cast<__nv_bfloat162*>(g_E_h);
    __nv_bfloat162* El2 = reinterpret_cast<__nv_bfloat162*>(g_E_l);
    Eh2[i * 2 + 0] = __nv_bfloat162(h0, h1);
    Eh2[i * 2 + 1] = __nv_bfloat162(h2, h3);
    El2[i * 2 + 0] = __nv_bfloat162(l0, l1);
    El2[i * 2 + 1] = __nv_bfloat162(l2, l3);
}

__global__ void mean_kernel(const float* __restrict__ enc_out) {
    int idx = blockIdx.x * 256 + threadIdx.x;   // B*ENC
    int b = idx / ENC, e = idx % ENC;
    const float* src = enc_out + (size_t)b * P * ENC + e;
    float s = 0.f;
#pragma unroll 4
    for (int p = 0; p < P; p++) s += src[(size_t)p * ENC];
    splitbf(s * (1.f / 196.f), g_mean_h[idx], g_mean_l[idx]);
}

__global__ void split_hc() {
    int idx = blockIdx.x * 256 + threadIdx.x;  // B*DEC
    int b = idx / DEC, d = idx % DEC;
    splitbf(g_hc[b * 2 * DEC + d], g_h_h[idx], g_h_l[idx]);
    g_c[idx] = g_hc[b * 2 * DEC + DEC + d];
}

// -------------------------- per-step kernels --------------------------------
__global__ void embed_kernel(const float* __restrict__ emb,
                             const int* __restrict__ cap, int t) {
    int b = blockIdx.x, tid = threadIdx.x;     // 128 threads
    int cidx = cap[b * T + t];
    const float4* src = reinterpret_cast<const float4*>(emb + (size_t)cidx * EMB);
    float4 v = src[tid];
    int o = b * XDIM + tid * 4;
    splitbf(v.x, g_x_h[o + 0], g_x_l[o + 0]);
    splitbf(v.y, g_x_h[o + 1], g_x_l[o + 1]);
    splitbf(v.z, g_x_h[o + 2], g_x_l[o + 2]);
    splitbf(v.w, g_x_h[o + 3], g_x_l[o + 3]);
}

// Fused scores + softmax: one block per batch row.
__global__ void scores_softmax_kernel(const float* __restrict__ w_att,
                                      const float* __restrict__ b_att) {
    __shared__ float s_dec[ATT];
    __shared__ float s_w[ATT];
    __shared__ float s_sc[P];
    __shared__ float red[256];
    int b = blockIdx.x, tid = threadIdx.x;
    int warp = tid >> 5, lane = tid & 31;
    for (int i = tid; i < ATT; i += 256) {
        s_dec[i] = g_hall[b * HALLN + i];
        s_w[i]   = w_att[i];
    }
    __syncthreads();
    float batt = b_att[0];
    for (int p = warp; p < P; p += 8) {
        const float* ep = &g_encproj[((size_t)(b * P + p)) * ATT];
        float s = 0.f;
#pragma unroll 4
        for (int a = lane; a < ATT; a += 32) {
            float e = ep[a] + s_dec[a];
            s += fmaxf(e, 0.f) * s_w[a];
        }
#pragma unroll
        for (int o = 16; o; o >>= 1) s += __shfl_down_sync(0xffffffffu, s, o);
        if (lane == 0) s_sc[p] = s + batt;
    }
    __syncthreads();
    float v = (tid < P) ? s_sc[tid] : -1e30f;
    red[tid] = v;
    __syncthreads();
    for (int o = 128; o; o >>= 1) {
        if (tid < o) red[tid] = fmaxf(red[tid], red[tid + o]);
        __syncthreads();
    }
    float m = red[0];
    __syncthreads();
    float e = (tid < P) ? expf(v - m) : 0.f;
    red[tid] = e;
    __syncthreads();
    for (int o = 128; o; o >>= 1) {
        if (tid < o) red[tid] += red[tid + o];
        __syncthreads();
    }
    if (tid < P) g_alpha[b * P + tid] = e / red[0];
}

// x[b, EMB+ch] = sigmoid(fbeta) * sum_p alpha[b,p]*enc_out[b,p,ch]  (fp32)
__global__ void context_kernel(const float* __restrict__ enc_out) {
    __shared__ float s_a[P];
    int b = blockIdx.x, tid = threadIdx.x;
    int ch = blockIdx.y * 256 + tid;
    if (tid < P) s_a[tid] = g_alpha[b * P + tid];
    __syncthreads();
    const float* eb = enc_out + (size_t)b * P * ENC + ch;
    float acc = 0.f;
#pragma unroll 4
    for (int p = 0; p < P; p++) acc = fmaf(s_a[p], eb[(size_t)p * ENC], acc);
    float gate = 1.f / (1.f + expf(-g_hall[b * HALLN + ATT + ch]));
    int o = b * XDIM + EMB + ch;
    splitbf(gate * acc, g_x_h[o], g_x_l[o]);
}

// Deterministic split-K reduce + LSTM cell; writes h planes + c.
__global__ void lstm_kernel() {
    int idx = blockIdx.x * 256 + threadIdx.x;  // B*DEC
    int b = idx / DEC, d = idx % DEC;
    const float* hallg = &g_hall[b * HALLN + ATT + ENC];
    float gi = hallg[d];
    float gf = hallg[DEC + d];
    float gg = hallg[2 * DEC + d];
    float go = hallg[3 * DEC + d];
#pragma unroll
    for (int s = 0; s < KSPLIT; s++) {
        const float* pp = &g_gpart[((size_t)s * B + b) * G4];
        gi += pp[d];
        gf += pp[DEC + d];
        gg += pp[2 * DEC + d];
        go += pp[3 * DEC + d];
    }
    float c  = g_c[idx];
    float si = 1.f / (1.f + expf(-gi));
    float sf = 1.f / (1.f + expf(-gf));
    float so = 1.f / (1.f + expf(-go));
    float cn = sf * c + si * tanhf(gg);
    float hn = so * tanhf(cn);
    g_c[idx] = cn;
    splitbf(hn, g_h_h[idx], g_h_l[idx]);
}

// ------------------------------- launcher -----------------------------------
extern "C" void kernel_launch(void* const* d_in, const int* in_sizes, int n_in,
                              void* d_out, int out_size) {
    const float* enc_out   = (const float*)d_in[0];
    const int*   captions  = (const int*)  d_in[1];
    const float* emb       = (const float*)d_in[2];
    const float* W_init_h  = (const float*)d_in[3];
    const float* b_init_h  = (const float*)d_in[4];
    const float* W_init_c  = (const float*)d_in[5];
    const float* b_init_c  = (const float*)d_in[6];
    const float* W_enc_att = (const float*)d_in[7];
    const float* b_enc_att = (const float*)d_in[8];
    const float* W_dec_att = (const float*)d_in[9];
    const float* b_dec_att = (const float*)d_in[10];
    const float* w_att     = (const float*)d_in[11];
    const float* b_att     = (const float*)d_in[12];
    const float* W_fbeta   = (const float*)d_in[13];
    const float* b_fbeta   = (const float*)d_in[14];
    const float* W_ih      = (const float*)d_in[15];
    const float* b_ih      = (const float*)d_in[16];
    const float* W_hh      = (const float*)d_in[17];
    const float* b_hh      = (const float*)d_in[18];
    const float* W_fc      = (const float*)d_in[19];
    const float* b_fc      = (const float*)d_in[20];
    float* out = (float*)d_out;

    bf16 *pMh, *pMl, *pHh, *pHl, *pXh, *pXl, *pEh, *pEl;
    bf16 *pWencH, *pWencL, *pWinH, *pWinL, *pWallH, *pWallL,
         *pWihH, *pWihL, *pWfcH, *pWfcL;
    float *p_hc, *p_encproj, *p_hall, *p_gpart, *p_ball, *p_binit;
    cudaGetSymbolAddress((void**)&pEh, g_E_h);
    cudaGetSymbolAddress((void**)&pEl, g_E_l);
    cudaGetSymbolAddress((void**)&pMh, g_mean_h);
    cudaGetSymbolAddress((void**)&pMl, g_mean_l);
    cudaGetSymbolAddress((void**)&pHh, g_h_h);
    cudaGetSymbolAddress((void**)&pHl, g_h_l);
    cudaGetSymbolAddress((void**)&pXh, g_x_h);
    cudaGetSymbolAddress((void**)&pXl, g_x_l);
    cudaGetSymbolAddress((void**)&pWencH, g_WencT_h);
    cudaGetSymbolAddress((void**)&pWencL, g_WencT_l);
    cudaGetSymbolAddress((void**)&pWinH, g_WinitT_h);
    cudaGetSymbolAddress((void**)&pWinL, g_WinitT_l);
    cudaGetSymbolAddress((void**)&pWallH, g_WallT_h);
    cudaGetSymbolAddress((void**)&pWallL, g_WallT_l);
    cudaGetSymbolAddress((void**)&pWihH, g_WihT_h);
    cudaGetSymbolAddress((void**)&pWihL, g_WihT_l);
    cudaGetSymbolAddress((void**)&pWfcH, g_WfcT_h);
    cudaGetSymbolAddress((void**)&pWfcL, g_WfcT_l);
    cudaGetSymbolAddress((void**)&p_hc, g_hc);
    cudaGetSymbolAddress((void**)&p_encproj, g_encproj);
    cudaGetSymbolAddress((void**)&p_hall, g_hall);
    cudaGetSymbolAddress((void**)&p_gpart, g_gpart);
    cudaGetSymbolAddress((void**)&p_ball, g_ball);
    cudaGetSymbolAddress((void**)&p_binit, g_binit);

    cudaFuncSetAttribute(gemm_bf3,
                         cudaFuncAttributeMaxDynamicSharedMemorySize,
                         GEMM_SMEM);

    // ---- one-time precompute (launch #4 = enc_proj GEMM for ncu) ----
    pack_weights<<<(STOT + 255) / 256, 256>>>(W_enc_att, W_init_h, W_init_c,
                                              W_dec_att, W_fbeta, W_hh, W_ih,
                                              W_fc);
    pack_bias<<<(HALLN + 2 * DEC + 255) / 256, 256>>>(b_dec_att, b_fbeta, b_hh,
                                                      b_ih, b_init_h, b_init_c);
    split_encout<<<(int)(((size_t)B * P * ENC / 4 + 255) / 256), 256>>>(enc_out);

    // enc_proj = enc_out @ W_enc_att + b  -> fp32 [25088, 512]
    gemm_bf3<<<dim3(ATT / 128, B * P / 128, 1), 256, GEMM_SMEM>>>(
        pEh, pEl, pWencH, pWencL, p_encproj, B * P, ATT, ENC, ATT, b_enc_att,
        ENC);

    mean_kernel<<<B * ENC / 256, 256>>>(enc_out);

    // [h0|c0] = mean @ [W_init_h|W_init_c] + b
    gemm_bf3<<<dim3(2 * DEC / 128, 1, 1), 256, GEMM_SMEM>>>(
        pMh, pMl, pWinH, pWinL, p_hc, B, 2 * DEC, ENC, 2 * DEC, p_binit, ENC);
    split_hc<<<B * DEC / 256, 256>>>();

    // ---- decode loop ----
    for (int t = 0; t < NSTEP; t++) {
        // hall = h @ [W_dec_att|W_fbeta|W_hh] + ball    [128, 4608]
        gemm_bf3<<<dim3(HALLN / 128, 1, 1), 256, GEMM_SMEM>>>(
            pHh, pHl, pWallH, pWallL, p_hall, B, HALLN, DEC, HALLN, p_ball,
            DEC);

        embed_kernel<<<B, 128>>>(emb, captions, t);
        scores_softmax_kernel<<<B, 256>>>(w_att, b_att);
        context_kernel<<<dim3(B, ENC / 256), 256>>>(enc_out);

        // gates partials = x @ W_ih, split-K over XDIM
        gemm_bf3<<<dim3(G4 / 128, 1, KSPLIT), 256, GEMM_SMEM>>>(
            pXh, pXl, pWihH, pWihL, p_gpart, B, G4, XDIM, G4, nullptr, KCHUNK);

        lstm_kernel<<<B * DEC / 256, 256>>>();

        // out[:, t, :] = h_new @ W_fc + b_fc
        gemm_bf3<<<dim3((VOC + 127) / 128, 1, 1), 256, GEMM_SMEM>>>(
            pHh, pHl, pWfcH, pWfcL, out + (size_t)t * VOC, B, VOC, DEC,
            NSTEP * VOC, b_fc, DEC);
    }
}